// round 16
// baseline (speedup 1.0000x reference)
#include <cuda_runtime.h>
#include <cstdint>

// minGRU bidirectional scan. R16 = R15 + conflict-free split-half ownership:
// thread t owns chunk f4s {t, 256+t} (two 4-elem chains) -> LDS.128 stride
// 16B across lanes (no bank conflicts, was 8-way). 2 interleaved scans.
// NT=256, 4 chunks of 2048, 2-stage TMA ring (33KB, 6 CTAs/SM).
// x: [B, 512, L] fp32 -> out: [B, 256, L] fp32.
//   out channel c2 (0..255): rev = c2>=128; h row = x[b,(rev?256:0)+(c2&127),:],
//   gate row = +128 channels. Recurrence (logical order; rev scans t=L-1..0):
//   out_t = a_t*out_{t-1} + b_t,  a = 1/(1+e^gate), b = (1-a)*g(h),
//   g(v) = v>=0 ? 1+v : e^v.

constexpr int L  = 8192;
constexpr int NT = 256;
constexpr int NW = NT / 32;    // 8 warps
constexpr int CE = 2048;       // elements per chunk
constexpr int CF = CE / 4;     // float4s per chunk = 512
constexpr int HF = CF / 2;     // f4s per half = 256
constexpr int CB = CE * 4;     // bytes per chunk row = 8 KB

// smem: stage s (0,1): h-chunk[CB] | g-chunk[CB]; then mbar[2]
constexpr int SMEM_BYTES = 2 * 2 * CB + 2 * 8;

__device__ __forceinline__ float fast_rcp(float v) {
    float r;
    asm("rcp.approx.f32 %0, %1;" : "=f"(r) : "f"(v));
    return r;
}

__device__ __forceinline__ void mbar_wait(uint32_t mbar, uint32_t parity) {
    uint32_t done;
    asm volatile(
        "{\n\t.reg .pred p;\n\t"
        "mbarrier.try_wait.parity.shared::cta.b64 p, [%1], %2;\n\t"
        "selp.b32 %0, 1, 0, p;\n\t}"
        : "=r"(done) : "r"(mbar), "r"(parity) : "memory");
    while (!done) {
        asm volatile(
            "{\n\t.reg .pred p;\n\t"
            "mbarrier.try_wait.parity.shared::cta.b64 p, [%1], %2, 0x989680;\n\t"
            "selp.b32 %0, 1, 0, p;\n\t}"
            : "=r"(done) : "r"(mbar), "r"(parity) : "memory");
    }
}

__device__ __forceinline__ void load_chunk(const float* hsrc, const float* gsrc,
                                           uint32_t hdst, uint32_t gdst,
                                           uint32_t mbar) {
    asm volatile("mbarrier.arrive.expect_tx.shared.b64 _, [%0], %1;"
                 :: "r"(mbar), "r"(2 * CB) : "memory");
    asm volatile("cp.async.bulk.shared::cta.global.mbarrier::complete_tx::bytes "
                 "[%0], [%1], %2, [%3];"
                 :: "r"(hdst), "l"(hsrc), "r"(CB), "r"(mbar) : "memory");
    asm volatile("cp.async.bulk.shared::cta.global.mbarrier::complete_tx::bytes "
                 "[%0], [%1], %2, [%3];"
                 :: "r"(gdst), "l"(gsrc), "r"(CB), "r"(mbar) : "memory");
}

__global__ __launch_bounds__(NT, 6)
void mingru_bidir_kernel(const float* __restrict__ x, float* __restrict__ out) {
    extern __shared__ float smem[];
    uint64_t* mbar64 = (uint64_t*)(smem + 4 * CF * 4);

    __shared__ float sA[2][2][NW], sB[2][2][NW];   // [stage][chain][warp]

    const int blk = blockIdx.x;
    const int b   = blk >> 8;
    const int c2  = blk & 255;
    const bool rev = (c2 & 128) != 0;
    const int hch = ((c2 & 128) ? 256 : 0) + (c2 & 127);

    const float* hrow = x + (size_t)(b * 512 + hch) * L;
    const float* grow = hrow + (size_t)128 * L;
    float4* __restrict__ o4 = (float4*)(out + (size_t)(b * 256 + c2) * L);

    const int tid  = threadIdx.x;
    const int lane = tid & 31;
    const int warp = tid >> 5;

    const uint32_t smem_u32 = (uint32_t)__cvta_generic_to_shared(smem);
    const uint32_t mbar_u32 = (uint32_t)__cvta_generic_to_shared(mbar64);

    if (tid == 0) {
        #pragma unroll
        for (int s = 0; s < 2; ++s)
            asm volatile("mbarrier.init.shared.b64 [%0], 1;"
                         :: "r"(mbar_u32 + 8 * s) : "memory");
        #pragma unroll
        for (int c = 0; c < 2; ++c) {
            const int p = rev ? (3 - c) : c;
            load_chunk(hrow + p * CE, grow + p * CE,
                       smem_u32 + (c & 1) * 2 * CB,
                       smem_u32 + (c & 1) * 2 * CB + CB,
                       mbar_u32 + 8 * (c & 1));
        }
    }
    __syncthreads();

    float carry = 0.0f;

    #pragma unroll
    for (int c = 0; c < 4; ++c) {
        const int s = c & 1;
        mbar_wait(mbar_u32 + 8 * s, (uint32_t)((c >> 1) & 1));

        const float4* h4 = (const float4*)(smem + s * 2 * CF * 4);
        const float4* g4 = h4 + CF;

        // chain q owns logical chunk f4 j_q = q*HF + tid (conflict-free LDS)
        int iq[2];
        #pragma unroll
        for (int q = 0; q < 2; ++q) {
            const int j = q * HF + tid;
            iq[q] = rev ? (CF - 1 - j) : j;
        }

        // ---- pointwise + per-chain compose ----
        float av[8], bv[8];
        float Aq[2], Bq[2];
        #pragma unroll
        for (int q = 0; q < 2; ++q) {
            float4 hv = h4[iq[q]];
            float4 gv = g4[iq[q]];
            if (rev) {
                hv = make_float4(hv.w, hv.z, hv.y, hv.x);
                gv = make_float4(gv.w, gv.z, gv.y, gv.x);
            }
            const float hh[4] = {hv.x, hv.y, hv.z, hv.w};
            const float gg[4] = {gv.x, gv.y, gv.z, gv.w};
            float A = 1.0f, B = 0.0f;
            #pragma unroll
            for (int k = 0; k < 4; ++k) {
                const float a  = fast_rcp(1.0f + __expf(gg[k]));
                const float gh = (hh[k] >= 0.0f) ? (1.0f + hh[k]) : __expf(hh[k]);
                const float bb = (1.0f - a) * gh;
                av[q * 4 + k] = a;
                bv[q * 4 + k] = bb;
                B = fmaf(B, a, bb);
                A *= a;
            }
            Aq[q] = A;
            Bq[q] = B;
        }

        // ---- warp inclusive scan, 2 chains interleaved ----
        #pragma unroll
        for (int off = 1; off < 32; off <<= 1) {
            #pragma unroll
            for (int q = 0; q < 2; ++q) {
                const float Au = __shfl_up_sync(0xFFFFFFFFu, Aq[q], off);
                const float Bu = __shfl_up_sync(0xFFFFFFFFu, Bq[q], off);
                if (lane >= off) {
                    Bq[q] = fmaf(Bu, Aq[q], Bq[q]);
                    Aq[q] *= Au;
                }
            }
        }
        float Ae[2], Be[2];
        #pragma unroll
        for (int q = 0; q < 2; ++q) {
            Ae[q] = __shfl_up_sync(0xFFFFFFFFu, Aq[q], 1);
            Be[q] = __shfl_up_sync(0xFFFFFFFFu, Bq[q], 1);
            if (lane == 0) { Ae[q] = 1.0f; Be[q] = 0.0f; }
            if (lane == 31) { sA[s][q][warp] = Aq[q]; sB[s][q][warp] = Bq[q]; }
        }
        __syncthreads();   // totals visible; stage s fully consumed

        // ---- refill freed stage with chunk c+2 (overlaps scan/replay/store) ----
        if (tid == 0 && c + 2 < 4) {
            const int p2 = rev ? (3 - (c + 2)) : (c + 2);
            load_chunk(hrow + p2 * CE, grow + p2 * CE,
                       smem_u32 + s * 2 * CB,
                       smem_u32 + s * 2 * CB + CB,
                       mbar_u32 + 8 * s);
        }

        // ---- redundant block scan over 8 warp totals, both chains ----
        float wa[2], wb[2];
        #pragma unroll
        for (int q = 0; q < 2; ++q) {
            wa[q] = sA[s][q][lane & (NW - 1)];
            wb[q] = sB[s][q][lane & (NW - 1)];
        }
        #pragma unroll
        for (int off = 1; off < NW; off <<= 1) {
            #pragma unroll
            for (int q = 0; q < 2; ++q) {
                const float Au = __shfl_up_sync(0xFFFFFFFFu, wa[q], off);
                const float Bu = __shfl_up_sync(0xFFFFFFFFu, wb[q], off);
                if (lane >= off) {
                    wb[q] = fmaf(Bu, wa[q], wb[q]);
                    wa[q] *= Au;
                }
            }
        }
        const int src = (warp == 0) ? 0 : (warp - 1);
        float prevA[2], prevB[2], totA[2], totB[2];
        #pragma unroll
        for (int q = 0; q < 2; ++q) {
            prevA[q] = __shfl_sync(0xFFFFFFFFu, wa[q], src);
            prevB[q] = __shfl_sync(0xFFFFFFFFu, wb[q], src);
            if (warp == 0) { prevA[q] = 1.0f; prevB[q] = 0.0f; }
            totA[q] = __shfl_sync(0xFFFFFFFFu, wa[q], NW - 1);
            totB[q] = __shfl_sync(0xFFFFFFFFu, wb[q], NW - 1);
        }

        // chain seeds: half0 starts from carry; half1 from state after half0
        float seed[2];
        seed[0] = carry;
        seed[1] = fmaf(totA[0], carry, totB[0]);

        // ---- replay (2 chains x 4) + 2 coalesced STG.128 ----
        #pragma unroll
        for (int q = 0; q < 2; ++q) {
            float st = fmaf(Ae[q], fmaf(prevA[q], seed[q], prevB[q]), Be[q]);
            float o[4];
            #pragma unroll
            for (int k = 0; k < 4; ++k) {
                st = fmaf(av[q * 4 + k], st, bv[q * 4 + k]);
                o[k] = st;
            }
            const int gf   = c * CF + q * HF + tid;       // logical global f4
            const int gidx = rev ? (L / 4 - 1 - gf) : gf; // physical f4
            o4[gidx] = rev ? make_float4(o[3], o[2], o[1], o[0])
                           : make_float4(o[0], o[1], o[2], o[3]);
        }

        carry = fmaf(totA[1], seed[1], totB[1]);   // state entering next chunk
    }
}

extern "C" void kernel_launch(void* const* d_in, const int* in_sizes, int n_in,
                              void* d_out, int out_size) {
    const float* x = (const float*)d_in[0];
    float* out = (float*)d_out;
    const int B = in_sizes[0] / (512 * L);
    cudaFuncSetAttribute(mingru_bidir_kernel,
                         cudaFuncAttributeMaxDynamicSharedMemorySize, SMEM_BYTES);
    mingru_bidir_kernel<<<B * 256, NT, SMEM_BYTES>>>(x, out);
}

// round 17
// speedup vs baseline: 1.0529x; 1.0529x over previous
#include <cuda_runtime.h>
#include <cstdint>

// minGRU bidirectional scan. R17 = R15 (best: NT=256, 4 chunks of 2048,
// EPT=8 contiguous, 2-stage TMA ring, 6 CTAs/SM) + pointwise issue diet:
// branchless g(h) via exp(min(h,0))+max(h,0), fused b = fma(-a, gh, gh).
// x: [B, 512, L] fp32 -> out: [B, 256, L] fp32.
//   out channel c2 (0..255): rev = c2>=128; h row = x[b,(rev?256:0)+(c2&127),:],
//   gate row = +128 channels. Recurrence (logical order; rev scans t=L-1..0):
//   out_t = a_t*out_{t-1} + b_t,  a = 1/(1+e^gate), b = (1-a)*g(h),
//   g(v) = v>=0 ? 1+v : e^v.

constexpr int L  = 8192;
constexpr int NT = 256;
constexpr int NW = NT / 32;    // 8 warps
constexpr int CE = 2048;       // elements per chunk
constexpr int CF = CE / 4;     // float4s per chunk = 512
constexpr int CB = CE * 4;     // bytes per chunk row = 8 KB

// smem: stage s (0,1): h-chunk[CB] | g-chunk[CB]; then mbar[2]
constexpr int SMEM_BYTES = 2 * 2 * CB + 2 * 8;

__device__ __forceinline__ float fast_rcp(float v) {
    float r;
    asm("rcp.approx.f32 %0, %1;" : "=f"(r) : "f"(v));
    return r;
}

__device__ __forceinline__ void mbar_wait(uint32_t mbar, uint32_t parity) {
    uint32_t done;
    asm volatile(
        "{\n\t.reg .pred p;\n\t"
        "mbarrier.try_wait.parity.shared::cta.b64 p, [%1], %2;\n\t"
        "selp.b32 %0, 1, 0, p;\n\t}"
        : "=r"(done) : "r"(mbar), "r"(parity) : "memory");
    while (!done) {
        asm volatile(
            "{\n\t.reg .pred p;\n\t"
            "mbarrier.try_wait.parity.shared::cta.b64 p, [%1], %2, 0x989680;\n\t"
            "selp.b32 %0, 1, 0, p;\n\t}"
            : "=r"(done) : "r"(mbar), "r"(parity) : "memory");
    }
}

__device__ __forceinline__ void load_chunk(const float* hsrc, const float* gsrc,
                                           uint32_t hdst, uint32_t gdst,
                                           uint32_t mbar) {
    asm volatile("mbarrier.arrive.expect_tx.shared.b64 _, [%0], %1;"
                 :: "r"(mbar), "r"(2 * CB) : "memory");
    asm volatile("cp.async.bulk.shared::cta.global.mbarrier::complete_tx::bytes "
                 "[%0], [%1], %2, [%3];"
                 :: "r"(hdst), "l"(hsrc), "r"(CB), "r"(mbar) : "memory");
    asm volatile("cp.async.bulk.shared::cta.global.mbarrier::complete_tx::bytes "
                 "[%0], [%1], %2, [%3];"
                 :: "r"(gdst), "l"(gsrc), "r"(CB), "r"(mbar) : "memory");
}

__global__ __launch_bounds__(NT, 6)
void mingru_bidir_kernel(const float* __restrict__ x, float* __restrict__ out) {
    extern __shared__ float smem[];
    uint64_t* mbar64 = (uint64_t*)(smem + 4 * CF * 4);   // after 2 stages x (h+g)

    __shared__ float sA[2][NW], sB[2][NW];

    const int blk = blockIdx.x;
    const int b   = blk >> 8;
    const int c2  = blk & 255;
    const bool rev = (c2 & 128) != 0;
    const int hch = ((c2 & 128) ? 256 : 0) + (c2 & 127);

    const float* hrow = x + (size_t)(b * 512 + hch) * L;
    const float* grow = hrow + (size_t)128 * L;
    float4* __restrict__ o4 = (float4*)(out + (size_t)(b * 256 + c2) * L);

    const int tid  = threadIdx.x;
    const int lane = tid & 31;
    const int warp = tid >> 5;

    const uint32_t smem_u32 = (uint32_t)__cvta_generic_to_shared(smem);
    const uint32_t mbar_u32 = (uint32_t)__cvta_generic_to_shared(mbar64);

    // ---- init barriers, load chunks 0 and 1 into stages 0 and 1 ----
    if (tid == 0) {
        #pragma unroll
        for (int s = 0; s < 2; ++s)
            asm volatile("mbarrier.init.shared.b64 [%0], 1;"
                         :: "r"(mbar_u32 + 8 * s) : "memory");
        #pragma unroll
        for (int c = 0; c < 2; ++c) {
            const int p = rev ? (3 - c) : c;       // physical chunk
            load_chunk(hrow + p * CE, grow + p * CE,
                       smem_u32 + (c & 1) * 2 * CB,
                       smem_u32 + (c & 1) * 2 * CB + CB,
                       mbar_u32 + 8 * (c & 1));
        }
    }
    __syncthreads();   // mbarrier inits visible before any try_wait

    float carry = 0.0f;

    #pragma unroll
    for (int c = 0; c < 4; ++c) {
        const int s = c & 1;                       // ring stage
        mbar_wait(mbar_u32 + 8 * s, (uint32_t)((c >> 1) & 1));

        const float4* h4 = (const float4*)(smem + s * 2 * CF * 4);
        const float4* g4 = h4 + CF;

        // thread owns logical f4 pair j0=2t, j1=2t+1 within the chunk
        const int j0 = 2 * tid;
        const int i0 = rev ? (CF - 1 - j0) : j0;
        const int i1 = rev ? (CF - 2 - j0) : (j0 + 1);

        float4 ha = h4[i0], hb = h4[i1];
        float4 ga = g4[i0], gb = g4[i1];
        if (rev) {
            ha = make_float4(ha.w, ha.z, ha.y, ha.x);
            hb = make_float4(hb.w, hb.z, hb.y, hb.x);
            ga = make_float4(ga.w, ga.z, ga.y, ga.x);
            gb = make_float4(gb.w, gb.z, gb.y, gb.x);
        }
        const float hv[8] = {ha.x, ha.y, ha.z, ha.w, hb.x, hb.y, hb.z, hb.w};
        const float gv[8] = {ga.x, ga.y, ga.z, ga.w, gb.x, gb.y, gb.z, gb.w};

        // ---- pointwise + thread compose (8 elems, one chain) ----
        // a  = 1/(1+e^g)
        // gh = e^{min(h,0)} + max(h,0)   (== h>=0 ? 1+h : e^h, branchless)
        // b  = (1-a)*gh = fma(-a, gh, gh)
        float av[8], bv[8];
        float A = 1.0f, B = 0.0f;
        #pragma unroll
        for (int k = 0; k < 8; ++k) {
            const float a  = fast_rcp(1.0f + __expf(gv[k]));
            const float gh = __expf(fminf(hv[k], 0.0f)) + fmaxf(hv[k], 0.0f);
            const float bb = fmaf(-a, gh, gh);
            av[k] = a;
            bv[k] = bb;
            B = fmaf(B, a, bb);
            A *= a;
        }

        // ---- warp inclusive scan (single chain) ----
        #pragma unroll
        for (int off = 1; off < 32; off <<= 1) {
            const float Au = __shfl_up_sync(0xFFFFFFFFu, A, off);
            const float Bu = __shfl_up_sync(0xFFFFFFFFu, B, off);
            if (lane >= off) {
                B = fmaf(Bu, A, B);
                A *= Au;
            }
        }
        float Ae = __shfl_up_sync(0xFFFFFFFFu, A, 1);
        float Be = __shfl_up_sync(0xFFFFFFFFu, B, 1);
        if (lane == 0) { Ae = 1.0f; Be = 0.0f; }

        if (lane == 31) { sA[s][warp] = A; sB[s][warp] = B; }
        __syncthreads();   // totals visible; stage s fully consumed

        // ---- refill: stage s free -> TMA chunk c+2 (overlaps the rest) ----
        if (tid == 0 && c + 2 < 4) {
            const int p2 = rev ? (3 - (c + 2)) : (c + 2);
            load_chunk(hrow + p2 * CE, grow + p2 * CE,
                       smem_u32 + s * 2 * CB,
                       smem_u32 + s * 2 * CB + CB,
                       mbar_u32 + 8 * s);
        }

        // ---- redundant block scan: every warp scans the 8 warp totals ----
        float wa = sA[s][lane & (NW - 1)];
        float wb = sB[s][lane & (NW - 1)];
        #pragma unroll
        for (int off = 1; off < NW; off <<= 1) {
            const float Au = __shfl_up_sync(0xFFFFFFFFu, wa, off);
            const float Bu = __shfl_up_sync(0xFFFFFFFFu, wb, off);
            if (lane >= off) {
                wb = fmaf(Bu, wa, wb);
                wa *= Au;
            }
        }
        const int src = (warp == 0) ? 0 : (warp - 1);
        float prevA = __shfl_sync(0xFFFFFFFFu, wa, src);
        float prevB = __shfl_sync(0xFFFFFFFFu, wb, src);
        if (warp == 0) { prevA = 1.0f; prevB = 0.0f; }
        const float totA = __shfl_sync(0xFFFFFFFFu, wa, NW - 1);
        const float totB = __shfl_sync(0xFFFFFFFFu, wb, NW - 1);

        // ---- replay (8 elems) + 2 coalesced STG.128 ----
        float st = fmaf(Ae, fmaf(prevA, carry, prevB), Be);
        float o[8];
        #pragma unroll
        for (int k = 0; k < 8; ++k) {
            st = fmaf(av[k], st, bv[k]);
            o[k] = st;
        }
        // logical f4 in sequence = c*CF + j -> physical global f4
        const int gf0 = c * CF + j0;
        const int go0 = rev ? (L / 4 - 1 - gf0) : gf0;
        const int go1 = rev ? (L / 4 - 2 - gf0) : (gf0 + 1);
        if (!rev) {
            o4[go0] = make_float4(o[0], o[1], o[2], o[3]);
            o4[go1] = make_float4(o[4], o[5], o[6], o[7]);
        } else {
            o4[go0] = make_float4(o[3], o[2], o[1], o[0]);
            o4[go1] = make_float4(o[7], o[6], o[5], o[4]);
        }

        carry = fmaf(totA, carry, totB);   // state entering next chunk
    }
}

extern "C" void kernel_launch(void* const* d_in, const int* in_sizes, int n_in,
                              void* d_out, int out_size) {
    const float* x = (const float*)d_in[0];
    float* out = (float*)d_out;
    const int B = in_sizes[0] / (512 * L);
    cudaFuncSetAttribute(mingru_bidir_kernel,
                         cudaFuncAttributeMaxDynamicSharedMemorySize, SMEM_BYTES);
    mingru_bidir_kernel<<<B * 256, NT, SMEM_BYTES>>>(x, out);
}